// round 11
// baseline (speedup 1.0000x reference)
#include <cuda_runtime.h>
#include <cstdint>

#define BATCH 256
#define L 4096
#define H 128

// ---------- packed f32x2 helpers (Blackwell sm_103a) ----------
__device__ __forceinline__ uint64_t pack2f(float a, float b) {
    uint64_t r; asm("mov.b64 %0, {%1, %2};" : "=l"(r) : "f"(a), "f"(b)); return r;
}
__device__ __forceinline__ float hsum2(uint64_t v) {
    float a, b; asm("mov.b64 {%0, %1}, %2;" : "=f"(a), "=f"(b) : "l"(v)); return a + b;
}
__device__ __forceinline__ uint64_t ffma2(uint64_t a, uint64_t b, uint64_t c) {
    uint64_t d; asm("fma.rn.f32x2 %0, %1, %2, %3;" : "=l"(d) : "l"(a), "l"(b), "l"(c)); return d;
}
__device__ __forceinline__ uint64_t fadd2(uint64_t a, uint64_t b) {
    uint64_t d; asm("add.rn.f32x2 %0, %1, %2;" : "=l"(d) : "l"(a), "l"(b)); return d;
}
__device__ __forceinline__ float elu1(float x) {
    return fmaxf(x, 0.f) + (__expf(fminf(x, 0.f)) - 1.f);
}
__device__ __forceinline__ uint32_t smem_u32(const void* p) {
    return (uint32_t)__cvta_generic_to_shared(p);
}

#define MB_INIT(addr, cnt) \
    asm volatile("mbarrier.init.shared.b64 [%0], %1;" :: "r"(addr), "r"(cnt) : "memory")
#define MB_ARRIVE(addr) \
    asm volatile("mbarrier.arrive.shared.b64 _, [%0];" :: "r"(addr) : "memory")
#define MB_WAIT(addr, par) do {                                              \
    asm volatile("{\n\t.reg .pred P;\n\t"                                    \
                 "WL_%=:\n\t"                                                \
                 "mbarrier.try_wait.parity.acquire.cta.shared::cta.b64 P, [%0], %1;\n\t" \
                 "@P bra WD_%=;\n\t"                                         \
                 "bra WL_%=;\n\t"                                            \
                 "WD_%=:\n\t}"                                               \
                 :: "r"(addr), "r"(par) : "memory");                         \
} while (0)

// One CTA = 2 batch elements, 256 threads = (i = tid>>1, s = tid&1), R4 layout.
// TWO-PHASE PIPELINE per iteration (t = 0..L):
//   phase 1: layer-1 step t   (reads h1 ring slot t-1, writes slot t), gated by mbar1
//   phase 2: layer-2 step t-1 (reads h2 ping-pong + h1 ring slot t-1), gated by mbar2
// mbarriers (count 8 = 1 elected arrive/warp) let warps pass gates individually:
// each warp's phase-2 work staggers against other warps' phase-1 LDS bursts,
// de-bursting the L1tex queue that the single __syncthreads convoy created.
// Skew bound: a warp at iter t passed wait(phase t-1) => all warps finished
// iter t-1 => ring/prod reuse distances (4, 2, 32 slots) are race-free.
__global__ void __launch_bounds__(256, 1)
rnn_scan_kernel(const int* __restrict__ x,
                const float* __restrict__ W_in,
                const float* __restrict__ W_c,
                const float* __restrict__ W_out,
                const float* __restrict__ b_out,
                float* __restrict__ out)
{
    __shared__ __align__(16) float sh_h1[4][2 * H];     // h1 ring: slot t&3
    __shared__ __align__(16) float sh_h2[2][2 * H];     // h2 ping-pong: slot u&1
    __shared__ __align__(16) float sh_r[3 * H];
    __shared__ __align__(16) float sh_prod[32][2 * H];  // 32 KB head ring
    __shared__ uint8_t sh_x[2 * L];
    __shared__ float sh_acc[8][2];
    __shared__ __align__(8) unsigned long long sh_mb[2];

    const int tid  = threadIdx.x;
    const int warp = tid >> 5;
    const int lane = tid & 31;
    const int i    = tid >> 1;
    const int s    = tid & 1;
    const int b0   = blockIdx.x * 2;

    // ---- stage x; r table; initial states h1(-1)=0 (slot 3), h2(-1)=0 (slot 1) ----
    const int* xg = x + (size_t)b0 * L;
    #pragma unroll 4
    for (int idx = tid; idx < 2 * L; idx += 256) sh_x[idx] = (uint8_t)xg[idx];
    if (tid < 2 * H) sh_r[tid] = elu1(W_in[tid]);
    if (tid < H)     sh_r[2 * H + tid] = 0.f;
    if (tid < 2 * H) { sh_h1[3][tid] = 0.f; sh_h2[1][tid] = 0.f; }

    const uint32_t mb1 = smem_u32(&sh_mb[0]);
    const uint32_t mb2 = smem_u32(&sh_mb[1]);
    if (tid == 0) { MB_INIT(mb1, 8); MB_INIT(mb2, 8); }

    // ---- weights in registers (R4 layout) ----
    uint64_t w1p[32], w2p[32];
    {
        const float* Wc0 = W_c;
        const float* Wc1 = W_c + H * H;
        #pragma unroll
        for (int j = 0; j < 16; ++j) {
            const int k0 = 8 * j + 4 * s;
            w1p[2*j]   = pack2f(Wc0[(k0+0)*H + i], Wc0[(k0+1)*H + i]);
            w1p[2*j+1] = pack2f(Wc0[(k0+2)*H + i], Wc0[(k0+3)*H + i]);
            w2p[2*j]   = pack2f(Wc1[(k0+0)*H + i], Wc1[(k0+1)*H + i]);
            w2p[2*j+1] = pack2f(Wc1[(k0+2)*H + i], Wc1[(k0+3)*H + i]);
        }
    }
    const float wout_i = W_out[i];
    const float bout   = b_out[0];
    float hacc0 = 0.f, hacc1 = 0.f;

    __syncthreads();   // mbar init + smem init visible

    for (int t = 0; t <= L; ++t) {
        // ================= phase 1: layer-1 step t =================
        if (t > 0) { if (lane == 0) MB_WAIT(mb1, (t - 1) & 1); __syncwarp(); }
        if (t < L) {
            const float* h1r = &sh_h1[(t + 3) & 3][0];
            float*       h1w = &sh_h1[t & 3][0];
            const int   prev = t ? (int)sh_x[s * L + t - 1] : 2;
            const float rv   = sh_r[prev * H + i];

            uint64_t a00 = 0, a01 = 0, a10 = 0, a11 = 0;
            #pragma unroll
            for (int j = 0; j < 16; ++j) {
                const int o = 8 * j + 4 * s;
                const ulonglong2 g0 = *(const ulonglong2*)(h1r + o);
                const ulonglong2 g1 = *(const ulonglong2*)(h1r + H + o);
                a00 = ffma2(w1p[2*j],   g0.x, a00);
                a01 = ffma2(w1p[2*j+1], g0.y, a01);
                a10 = ffma2(w1p[2*j],   g1.x, a10);
                a11 = ffma2(w1p[2*j+1], g1.y, a11);
            }
            float p0 = hsum2(fadd2(a00, a01));
            float p1 = hsum2(fadd2(a10, a11));
            p0 += __shfl_xor_sync(0xffffffffu, p0, 1);
            p1 += __shfl_xor_sync(0xffffffffu, p1, 1);

            const float h1n = elu1(s ? p1 : p0) + rv;
            h1w[s * H + i] = h1n;
            __syncwarp();             // order STS before elected arrive
        }
        if (lane == 0) MB_ARRIVE(mb1);

        // ================= phase 2: layer-2 step u = t-1 =================
        if (t > 0) {
            if (lane == 0) MB_WAIT(mb2, (t - 1) & 1);
            __syncwarp();
            const int u = t - 1;
            const float* h2r = &sh_h2[(u & 1) ^ 1][0];   // h2(u-1)
            float*       h2w = &sh_h2[u & 1][0];
            const float  h1u = sh_h1[u & 3][s * H + i];  // h1(u), synced via mb1

            uint64_t c00 = 0, c01 = 0, c10 = 0, c11 = 0;
            #pragma unroll
            for (int j = 0; j < 16; ++j) {
                const int o = 8 * j + 4 * s;
                const ulonglong2 e0 = *(const ulonglong2*)(h2r + o);
                const ulonglong2 e1 = *(const ulonglong2*)(h2r + H + o);
                c00 = ffma2(w2p[2*j],   e0.x, c00);
                c01 = ffma2(w2p[2*j+1], e0.y, c01);
                c10 = ffma2(w2p[2*j],   e1.x, c10);
                c11 = ffma2(w2p[2*j+1], e1.y, c11);
            }
            float q0 = hsum2(fadd2(c00, c01));
            float q1 = hsum2(fadd2(c10, c11));
            q0 += __shfl_xor_sync(0xffffffffu, q0, 1);
            q1 += __shfl_xor_sync(0xffffffffu, q1, 1);

            const float h2n = elu1(s ? q1 : q0) + h1u;
            h2w[s * H + i] = h2n;
            sh_prod[u & 31][s * H + i] = h2n * wout_i;

            // amortized head: window [u-16, u-1] (slots synced via mb2 phase t-1)
            if ((u & 15) == 0 && u > 0) {
                #pragma unroll
                for (int e = 0; e < 2; ++e) {
                    const int v    = u - 16 + 2 * warp + e;
                    const int slot = v & 31;
                    #pragma unroll
                    for (int b = 0; b < 2; ++b) {
                        const float4 vv = *(const float4*)&sh_prod[slot][b * H + lane * 4];
                        float sr = (vv.x + vv.y) + (vv.z + vv.w);
                        #pragma unroll
                        for (int off = 16; off; off >>= 1)
                            sr += __shfl_xor_sync(0xffffffffu, sr, off);
                        const float logit = sr + bout;
                        const int   xt    = sh_x[b * L + v];
                        const float m     = fmaxf(logit, 0.f);
                        const float lse   = m + __logf(__expf(-m) + __expf(logit - m));
                        const float gv    = 0.5f * ((xt ? logit : 0.f) - lse);
                        if (b == 0) hacc0 += gv; else hacc1 += gv;
                    }
                }
            }
            __syncwarp();             // order STS before elected arrive
        }
        if (lane == 0) MB_ARRIVE(mb2);
    }

    __syncthreads();

    // ===== epilogue: last 16 slots [L-16, L-1], 2 per warp, both batches =====
    #pragma unroll
    for (int e = 0; e < 2; ++e) {
        const int v    = L - 16 + 2 * warp + e;
        const int slot = v & 31;
        #pragma unroll
        for (int b = 0; b < 2; ++b) {
            const float4 vv = *(const float4*)&sh_prod[slot][b * H + lane * 4];
            float sr = (vv.x + vv.y) + (vv.z + vv.w);
            #pragma unroll
            for (int off = 16; off; off >>= 1)
                sr += __shfl_xor_sync(0xffffffffu, sr, off);
            const float logit = sr + bout;
            const int   xt    = sh_x[b * L + v];
            const float m     = fmaxf(logit, 0.f);
            const float lse   = m + __logf(__expf(-m) + __expf(logit - m));
            const float gv    = 0.5f * ((xt ? logit : 0.f) - lse);
            if (b == 0) hacc0 += gv; else hacc1 += gv;
        }
    }

    if (lane == 0) { sh_acc[warp][0] = hacc0; sh_acc[warp][1] = hacc1; }
    __syncthreads();
    if (tid < 2) {
        float a = 0.f;
        #pragma unroll
        for (int w = 0; w < 8; ++w) a += sh_acc[w][tid];
        out[b0 + tid] = a;
    }
}

extern "C" void kernel_launch(void* const* d_in, const int* in_sizes, int n_in,
                              void* d_out, int out_size)
{
    const int*   x     = (const int*)  d_in[0];
    const float* W_in  = (const float*)d_in[1];
    const float* W_c   = (const float*)d_in[2];
    const float* W_out = (const float*)d_in[3];
    const float* b_out = (const float*)d_in[4];

    rnn_scan_kernel<<<BATCH / 2, 256>>>(x, W_in, W_c, W_out, b_out, (float*)d_out);
}

// round 12
// speedup vs baseline: 2.4997x; 2.4997x over previous
#include <cuda_runtime.h>
#include <cstdint>

#define BATCH 256
#define L 4096
#define H 128
#define RING 16

// ---------- packed f32x2 helpers (Blackwell sm_103a) ----------
__device__ __forceinline__ uint64_t pack2f(float a, float b) {
    uint64_t r; asm("mov.b64 %0, {%1, %2};" : "=l"(r) : "f"(a), "f"(b)); return r;
}
__device__ __forceinline__ float hsum2(uint64_t v) {
    float a, b; asm("mov.b64 {%0, %1}, %2;" : "=f"(a), "=f"(b) : "l"(v)); return a + b;
}
__device__ __forceinline__ uint64_t ffma2(uint64_t a, uint64_t b, uint64_t c) {
    uint64_t d; asm("fma.rn.f32x2 %0, %1, %2, %3;" : "=l"(d) : "l"(a), "l"(b), "l"(c)); return d;
}
__device__ __forceinline__ uint64_t fadd2(uint64_t a, uint64_t b) {
    uint64_t d; asm("add.rn.f32x2 %0, %1, %2;" : "=l"(d) : "l"(a), "l"(b)); return d;
}
__device__ __forceinline__ float elu1(float x) {
    return fmaxf(x, 0.f) + (__expf(fminf(x, 0.f)) - 1.f);
}
// cluster rank + generic-address peer mapping
__device__ __forceinline__ uint32_t ctarank() {
    uint32_t r; asm("mov.u32 %0, %%cluster_ctarank;" : "=r"(r)); return r;
}
template <typename T>
__device__ __forceinline__ T* mapa_ptr(T* p, uint32_t rank) {
    uint64_t r;
    asm("mapa.u64 %0, %1, %2;" : "=l"(r) : "l"((uint64_t)p), "r"(rank));
    return (T*)r;
}
__device__ __forceinline__ void st_release_cluster(unsigned* p, unsigned v) {
    asm volatile("st.release.cluster.u32 [%0], %1;" :: "l"(p), "r"(v) : "memory");
}
__device__ __forceinline__ unsigned ld_acquire_cluster(const unsigned* p) {
    unsigned v;
    asm volatile("ld.acquire.cluster.u32 %0, [%1];" : "=r"(v) : "l"(p) : "memory");
    return v;
}
#define CLUSTER_SYNC() do { \
    asm volatile("barrier.cluster.arrive.aligned;" ::: "memory"); \
    asm volatile("barrier.cluster.wait.aligned;"   ::: "memory"); \
} while (0)

// Cluster (2,1,1): rank 0 = layer-1 producer, rank 1 = layer-2 consumer + head.
// Both handle the same 2 batch elements {2k, 2k+1}, k = blockIdx.x>>1.
// (i = tid>>1, s = tid&1) layout: thread holds its k-half of ONE layer's W_c
// columns (64 floats = 32 packed regs) -> ~105 regs -> honest occupancy 2:
// every SM hosts 2 independent recurrences (4 decorrelated warps/SMSP).
// Producer -> consumer: h1(t) stored into consumer's 16-slot smem ring via
// mapa'd generic stores; published by ONE st.release.cluster flag per step
// after __syncthreads (cumulative release). Consumer tid0 spins on a LOCAL
// ld.acquire.cluster (fast path = 1 shared load). Backpressure: consumer
// reports consumed count every 4 steps; producer stays <= 14 steps ahead.
__global__ void __launch_bounds__(256, 2) __cluster_dims__(2, 1, 1)
rnn_cluster_kernel(const int* __restrict__ x,
                   const float* __restrict__ W_in,
                   const float* __restrict__ W_c,
                   const float* __restrict__ W_out,
                   const float* __restrict__ b_out,
                   float* __restrict__ out)
{
    __shared__ __align__(16) float sh_h[2][2 * H];        // h1 (rank0) / h2 (rank1) ping-pong
    __shared__ __align__(16) float sh_ring[RING][2 * H];  // rank1: h1 ring (16 KB)
    __shared__ __align__(16) float sh_prod[RING][2 * H];  // rank1: head ring (16 KB)
    __shared__ __align__(16) float sh_r[3 * H];           // rank0 only
    __shared__ uint8_t sh_x[2 * L];                       // both (8 KB)
    __shared__ float sh_acc[8][2];
    __shared__ unsigned sh_flag;     // rank1: published step count (written by rank0)
    __shared__ unsigned sh_credit;   // rank0: consumed step count (written by rank1)

    const int tid  = threadIdx.x;
    const int warp = tid >> 5;
    const int lane = tid & 31;
    const int i    = tid >> 1;
    const int s    = tid & 1;
    const uint32_t rank = ctarank();
    const int b0   = (blockIdx.x >> 1) * 2;

    // ---- common staging ----
    const int* xg = x + (size_t)b0 * L;
    #pragma unroll 4
    for (int idx = tid; idx < 2 * L; idx += 256) sh_x[idx] = (uint8_t)xg[idx];
    if (tid < 2 * H) sh_h[0][tid] = 0.f;
    if (tid == 0) { sh_flag = 0u; sh_credit = 0u; }

    const float* Wl = W_c + (rank ? H * H : 0);   // layer for this rank
    uint64_t w[32];
    #pragma unroll
    for (int j = 0; j < 16; ++j) {
        const int k0 = 8 * j + 4 * s;
        w[2*j]   = pack2f(Wl[(k0+0)*H + i], Wl[(k0+1)*H + i]);
        w[2*j+1] = pack2f(Wl[(k0+2)*H + i], Wl[(k0+3)*H + i]);
    }
    if (rank == 0) {
        if (tid < 2 * H) sh_r[tid] = elu1(W_in[tid]);
        if (tid < H)     sh_r[2 * H + tid] = 0.f;
    }
    __syncthreads();
    CLUSTER_SYNC();   // flags/rings initialized cluster-wide before any traffic

    if (rank == 0) {
        // ===================== PRODUCER: layer-1 scan =====================
        float*    peer_ring = mapa_ptr(&sh_ring[0][0], 1u);
        unsigned* peer_flag = mapa_ptr(&sh_flag, 1u);
        unsigned  cred = 0u;

        for (int t = 0; t < L; ++t) {
            const int p = t & 1;
            const float* hr = &sh_h[p][0];
            const int   prev = t ? (int)sh_x[s * L + t - 1] : 2;
            const float rv   = sh_r[prev * H + i];

            uint64_t a00 = 0, a01 = 0, a10 = 0, a11 = 0;
            #pragma unroll
            for (int j = 0; j < 16; ++j) {
                const int o = 8 * j + 4 * s;
                const ulonglong2 h0 = *(const ulonglong2*)(hr + o);
                const ulonglong2 h1 = *(const ulonglong2*)(hr + H + o);
                a00 = ffma2(w[2*j],   h0.x, a00);
                a01 = ffma2(w[2*j+1], h0.y, a01);
                a10 = ffma2(w[2*j],   h1.x, a10);
                a11 = ffma2(w[2*j+1], h1.y, a11);
            }
            float p0 = hsum2(fadd2(a00, a01));
            float p1 = hsum2(fadd2(a10, a11));
            p0 += __shfl_xor_sync(0xffffffffu, p0, 1);
            p1 += __shfl_xor_sync(0xffffffffu, p1, 1);

            const float h1n = elu1(s ? p1 : p0) + rv;
            sh_h[p ^ 1][s * H + i] = h1n;                        // own recurrence
            peer_ring[(t & (RING - 1)) * 2 * H + s * H + i] = h1n; // DSMEM store

            // gate NEXT step's slot (stay <= RING-2 ahead of consumer)
            if (tid == 0 && t + 1 < L) {
                const unsigned need = (unsigned)(t + 1);
                while (need > cred + (RING - 2)) cred = ld_acquire_cluster(&sh_credit);
            }
            __syncthreads();                                     // orders all DSMEM stores
            if (tid == 0) st_release_cluster(peer_flag, (unsigned)(t + 1));
        }
    } else {
        // ============== CONSUMER: layer-2 scan + log-prob head ==============
        unsigned* peer_credit = mapa_ptr(&sh_credit, 0u);
        const float wout_i = W_out[i];
        const float bout   = b_out[0];
        float hacc0 = 0.f, hacc1 = 0.f;
        unsigned flagv = 0u;

        for (int t = 0; t < L; ++t) {
            if (tid == 0) {
                const unsigned need = (unsigned)(t + 1);
                while (flagv < need) flagv = ld_acquire_cluster(&sh_flag);
            }
            __syncthreads();   // flag gate + h2 ping-pong + prod-ring visibility

            const int p = t & 1;
            const float* hr = &sh_h[p][0];
            const float h1v = sh_ring[t & (RING - 1)][s * H + i];

            uint64_t a00 = 0, a01 = 0, a10 = 0, a11 = 0;
            #pragma unroll
            for (int j = 0; j < 16; ++j) {
                const int o = 8 * j + 4 * s;
                const ulonglong2 h0 = *(const ulonglong2*)(hr + o);
                const ulonglong2 h1 = *(const ulonglong2*)(hr + H + o);
                a00 = ffma2(w[2*j],   h0.x, a00);
                a01 = ffma2(w[2*j+1], h0.y, a01);
                a10 = ffma2(w[2*j],   h1.x, a10);
                a11 = ffma2(w[2*j+1], h1.y, a11);
            }
            float p0 = hsum2(fadd2(a00, a01));
            float p1 = hsum2(fadd2(a10, a11));
            p0 += __shfl_xor_sync(0xffffffffu, p0, 1);
            p1 += __shfl_xor_sync(0xffffffffu, p1, 1);

            const float h2n = elu1(s ? p1 : p0) + h1v;
            sh_h[p ^ 1][s * H + i] = h2n;
            sh_prod[t & (RING - 1)][s * H + i] = h2n * wout_i;

            // amortized head: window [t-8, t-1], warp w -> slot t-8+w, both batches
            if ((t & 7) == 0 && t >= 8) {
                const int u = t - 8 + warp;
                #pragma unroll
                for (int b = 0; b < 2; ++b) {
                    const float4 v = *(const float4*)&sh_prod[u & (RING - 1)][b * H + lane * 4];
                    float sr = (v.x + v.y) + (v.z + v.w);
                    #pragma unroll
                    for (int off = 16; off; off >>= 1)
                        sr += __shfl_xor_sync(0xffffffffu, sr, off);
                    if (lane == 0) {
                        const float logit = sr + bout;
                        const int   xt    = sh_x[b * L + u];
                        const float m     = fmaxf(logit, 0.f);
                        const float lse   = m + __logf(__expf(-m) + __expf(logit - m));
                        const float gv    = 0.5f * ((xt ? logit : 0.f) - lse);
                        if (b == 0) hacc0 += gv; else hacc1 += gv;
                    }
                }
            }

            if ((t & 3) == 3 && tid == 0)
                st_release_cluster(peer_credit, (unsigned)(t + 1));
        }

        __syncthreads();
        // epilogue: last 8 slots [L-8, L-1]
        {
            const int u = L - 8 + warp;
            #pragma unroll
            for (int b = 0; b < 2; ++b) {
                const float4 v = *(const float4*)&sh_prod[u & (RING - 1)][b * H + lane * 4];
                float sr = (v.x + v.y) + (v.z + v.w);
                #pragma unroll
                for (int off = 16; off; off >>= 1)
                    sr += __shfl_xor_sync(0xffffffffu, sr, off);
                if (lane == 0) {
                    const float logit = sr + bout;
                    const int   xt    = sh_x[b * L + u];
                    const float m     = fmaxf(logit, 0.f);
                    const float lse   = m + __logf(__expf(-m) + __expf(logit - m));
                    const float gv    = 0.5f * ((xt ? logit : 0.f) - lse);
                    if (b == 0) hacc0 += gv; else hacc1 += gv;
                }
            }
        }
        if (lane == 0) { sh_acc[warp][0] = hacc0; sh_acc[warp][1] = hacc1; }
        __syncthreads();
        if (tid < 2) {
            float a = 0.f;
            #pragma unroll
            for (int wq = 0; wq < 8; ++wq) a += sh_acc[wq][tid];
            out[b0 + tid] = a;
        }
    }

    CLUSTER_SYNC();   // no CTA exits while the peer may still target its smem
}

extern "C" void kernel_launch(void* const* d_in, const int* in_sizes, int n_in,
                              void* d_out, int out_size)
{
    const int*   x     = (const int*)  d_in[0];
    const float* W_in  = (const float*)d_in[1];
    const float* W_c   = (const float*)d_in[2];
    const float* W_out = (const float*)d_in[3];
    const float* b_out = (const float*)d_in[4];

    rnn_cluster_kernel<<<BATCH, 256>>>(x, W_in, W_c, W_out, b_out, (float*)d_out);
}